// round 14
// baseline (speedup 1.0000x reference)
#include <cuda_runtime.h>
#include <cuda_bf16.h>
#include <cstdint>

// Problem constants (shapes fixed by setup_inputs)
#define HW      (1024 * 1024)             // pixels per channel
#define NBINS   16
#define NTOT    (NBINS * NBINS * NBINS)   // 4096
#define NPAIR   (NTOT / 2)                // 2048 paired (64-bit) bins
#define NIMG    9                         // 8 input images + 1 style image
#define BPI     48                        // blocks per image
#define TPB     256                       // threads per block
#define NCTA    (BPI * NIMG)              // 432 CTAs (single wave @ 3/SM, 64KB smem)

#define SLOTS   4                         // bank-sliced sub-histograms
#define SMEM_BYTES (SLOTS * NTOT * 4)     // 64 KB dynamic shared

#define LOSS_CTAS  16
#define LOSS_TPB   128                    // 16*128 = 2048 = NPAIR threads

// Global scratch (zero-initialized at module load; loss kernel re-zeros its
// own state after each use, so every graph replay sees clean state).
__device__ unsigned long long g_hist2[NIMG][NPAIR];
__device__ unsigned int       g_loss_acc;   // exact integer L1 sum
__device__ unsigned int       g_done;       // ticket for last-CTA detection

// Bank-flattening bin permutation: low 4 bits become (r+g+b) mod 16, so the
// Gaussian-tail-heavy channel bins spread evenly across banks (3-fold mod-16
// convolution flattens the 19% tail spikes to within ~2% of uniform).
// Bijective: within fixed high bits, low4 -> low4+const (mod 16).
__device__ __forceinline__ int sbin(int f) {
    return (f & 0xFF0) | ((f + (f >> 4) + (f >> 8)) & 15);
}

// searchsorted(boundaries, v, side='left') with boundaries = i/8 - 1, i=1..15.
// = count of boundaries strictly < v = clamp(ceil(8*(v+1)) - 1, 0, 15).
__device__ __forceinline__ int bin_of(float v) {
    int i = __float2int_ru(fmaf(v, 8.0f, 8.0f)) - 1;   // single F2I.CEIL
    i = max(i, 0);
    i = min(i, 15);
    return i;
}

__device__ __forceinline__ int flat_bin(float r, float g, float b) {
    return bin_of(r) + (bin_of(g) << 4) + (bin_of(b) << 8);
}

// ---------------------------------------------------------------------------
// Kernel A: per-image histogram. grid = (BPI, NIMG), block = TPB, 64KB smem.
// 4 bank-sliced sub-histograms: word = 4*sbin(f) + (lane&3).
// bank mod 4 == lane mod 4, so each 8-lane group owns 8 exclusive banks
// (conflict degree E[max 8->8] ~= 2.3 instead of E[max 32->32] ~= 3.2).
// ---------------------------------------------------------------------------
__global__ __launch_bounds__(TPB) void hist_kernel(
    const float* __restrict__ inp,   // [8, 3, H, W]
    const float* __restrict__ sty)   // [1, 3, H, W]
{
    extern __shared__ int sh[];      // SLOTS * NTOT ints = 64 KB
    #pragma unroll
    for (int i = threadIdx.x; i < SLOTS * NTOT; i += TPB) sh[i] = 0;
    __syncthreads();

    const int img  = blockIdx.y;
    const int slot = threadIdx.x & (SLOTS - 1);
    const float* base = (img < 8) ? (inp + (size_t)img * 3 * HW) : sty;

    const float4* r4 = (const float4*)(base);
    const float4* g4 = (const float4*)(base + HW);
    const float4* b4 = (const float4*)(base + 2 * HW);

    const int nvec      = HW / 4;                    // 262144 float4/channel
    const int per_block = (nvec + BPI - 1) / BPI;    // 5462
    const int start     = blockIdx.x * per_block;
    const int end       = min(start + per_block, nvec);

    #pragma unroll 2
    for (int i = start + threadIdx.x; i < end; i += TPB) {
        float4 r = r4[i];
        float4 g = g4[i];
        float4 b = b4[i];

        atomicAdd(&sh[sbin(flat_bin(r.x, g.x, b.x)) * SLOTS + slot], 1);
        atomicAdd(&sh[sbin(flat_bin(r.y, g.y, b.y)) * SLOTS + slot], 1);
        atomicAdd(&sh[sbin(flat_bin(r.z, g.z, b.z)) * SLOTS + slot], 1);
        atomicAdd(&sh[sbin(flat_bin(r.w, g.w, b.w)) * SLOTS + slot], 1);
    }
    __syncthreads();

    // Flush: sum the 4 slots per bin, pack two adjacent f-bins into one
    // 64-bit atomic (pruned on zero).
    #pragma unroll
    for (int fp = threadIdx.x; fp < NPAIR; fp += TPB) {
        const int w0 = sbin(2 * fp)     * SLOTS;
        const int w1 = sbin(2 * fp + 1) * SLOTS;
        unsigned int lo = 0, hi = 0;
        #pragma unroll
        for (int s = 0; s < SLOTS; s++) {
            lo += (unsigned int)sh[w0 + s];
            hi += (unsigned int)sh[w1 + s];
        }
        if (lo | hi) {
            atomicAdd(&g_hist2[img][fp],
                      (unsigned long long)lo | ((unsigned long long)hi << 32));
        }
    }
}

// ---------------------------------------------------------------------------
// Kernel B: parallel loss + scratch reset. grid = LOSS_CTAS, block = LOSS_TPB.
// Launched with PDL (programmatic stream serialization) so its launch ramp
// overlaps the hist kernel's tail; cudaGridDependencySynchronize() gates the
// dependent reads.
// ---------------------------------------------------------------------------
__global__ __launch_bounds__(LOSS_TPB) void loss_kernel(float* __restrict__ out)
{
    cudaGridDependencySynchronize();   // wait for hist kernel's results

    const int i = blockIdx.x * LOSS_TPB + threadIdx.x;   // pair index, < NPAIR

    // 9 independent loads (batched for MLP)
    unsigned long long ps = g_hist2[8][i];
    unsigned long long p0 = g_hist2[0][i];
    unsigned long long p1 = g_hist2[1][i];
    unsigned long long p2 = g_hist2[2][i];
    unsigned long long p3 = g_hist2[3][i];
    unsigned long long p4 = g_hist2[4][i];
    unsigned long long p5 = g_hist2[5][i];
    unsigned long long p6 = g_hist2[6][i];
    unsigned long long p7 = g_hist2[7][i];

    int slo = (int)(unsigned int)ps;
    int shi = (int)(unsigned int)(ps >> 32);

    int acc = 0;   // max 2*8*HW = 16.8M < 2^31
    #define ABS_DIFF(p) do {                                   \
        int d0 = (int)(unsigned int)(p) - slo;                 \
        int d1 = (int)(unsigned int)((p) >> 32) - shi;         \
        acc += (d0 < 0 ? -d0 : d0) + (d1 < 0 ? -d1 : d1);      \
    } while (0)
    ABS_DIFF(p0); ABS_DIFF(p1); ABS_DIFF(p2); ABS_DIFF(p3);
    ABS_DIFF(p4); ABS_DIFF(p5); ABS_DIFF(p6); ABS_DIFF(p7);
    #undef ABS_DIFF

    // reset this thread's slice of the scratch for the next graph replay
    #pragma unroll
    for (int b = 0; b < NIMG; b++) g_hist2[b][i] = 0ULL;

    // block reduction
    #pragma unroll
    for (int o = 16; o > 0; o >>= 1)
        acc += __shfl_xor_sync(0xffffffffu, acc, o);

    __shared__ int warp_sum[LOSS_TPB / 32];
    if ((threadIdx.x & 31) == 0) warp_sum[threadIdx.x >> 5] = acc;
    __syncthreads();

    __shared__ unsigned int my_ticket;
    if (threadIdx.x == 0) {
        int blk = 0;
        #pragma unroll
        for (int w = 0; w < LOSS_TPB / 32; w++) blk += warp_sum[w];
        atomicAdd(&g_loss_acc, (unsigned int)blk);
        __threadfence();
        my_ticket = atomicAdd(&g_done, 1u);
    }
    __syncthreads();

    if (threadIdx.x == 0 && my_ticket == (unsigned int)(LOSS_CTAS - 1)) {
        unsigned int total = atomicAdd(&g_loss_acc, 0u);   // coherent read
        out[0] = (float)((double)total /
                         ((double)HW * 8.0 * (double)NTOT));
        g_loss_acc = 0u;
        g_done = 0u;
    }
}

// ---------------------------------------------------------------------------
// Launch contract
// ---------------------------------------------------------------------------
extern "C" void kernel_launch(void* const* d_in, const int* in_sizes, int n_in,
                              void* d_out, int out_size)
{
    const float* inp = (const float*)d_in[0];   // [8,3,1024,1024] fp32
    const float* sty = (const float*)d_in[1];   // [1,3,1024,1024] fp32
    float* out = (float*)d_out;

    static bool attr_done = false;
    if (!attr_done) {
        cudaFuncSetAttribute(hist_kernel,
                             cudaFuncAttributeMaxDynamicSharedMemorySize,
                             SMEM_BYTES);
        attr_done = true;
    }

    dim3 grid(BPI, NIMG);
    hist_kernel<<<grid, TPB, SMEM_BYTES>>>(inp, sty);

    // Loss kernel with programmatic dependent launch (overlap launch ramp
    // with hist tail; cudaGridDependencySynchronize() inside orders reads).
    cudaLaunchConfig_t cfg = {};
    cfg.gridDim  = dim3(LOSS_CTAS, 1, 1);
    cfg.blockDim = dim3(LOSS_TPB, 1, 1);
    cfg.dynamicSmemBytes = 0;
    cfg.stream = 0;
    cudaLaunchAttribute attrs[1];
    attrs[0].id = cudaLaunchAttributeProgrammaticStreamSerialization;
    attrs[0].val.programmaticStreamSerializationAllowed = 1;
    cfg.attrs = attrs;
    cfg.numAttrs = 1;
    cudaLaunchKernelEx(&cfg, loss_kernel, out);
}

// round 15
// speedup vs baseline: 1.1633x; 1.1633x over previous
#include <cuda_runtime.h>
#include <cuda_bf16.h>
#include <cstdint>

// Problem constants (shapes fixed by setup_inputs)
#define HW      (1024 * 1024)             // pixels per channel
#define NBINS   16
#define NTOT    (NBINS * NBINS * NBINS)   // 4096
#define NPAIR   (NTOT / 2)                // 2048 paired (64-bit) bins
#define NIMG    9                         // 8 input images + 1 style image
#define BPI     128                       // blocks per image
#define TPB     256                       // threads per block
#define NCTA    (BPI * NIMG)              // 1152 CTAs (single wave @ 8/SM)

#define LOSS_CTAS  16
#define LOSS_TPB   128                    // 16*128 = 2048 = NPAIR threads

// Global scratch (zero-initialized at module load; loss kernel re-zeros its
// own state after each use, so every graph replay sees clean state).
__device__ unsigned long long g_hist2[NIMG][NPAIR];
__device__ unsigned int       g_loss_acc;   // exact integer L1 sum
__device__ unsigned int       g_done;       // ticket for last-CTA detection

// Skewed shared-memory layout: rotate the low-5-bit lane (bank) by the row
// index so that the Gaussian-hot corner bins spread across banks instead of
// piling onto banks {0,15,16,31}. Bijective within each 32-entry row.
__device__ __forceinline__ int skew(int f) {
    return (f & ~31) | ((f + (f >> 5)) & 31);
}

// searchsorted(boundaries, v, side='left') with boundaries = i/8 - 1, i=1..15.
// = count of boundaries strictly < v = clamp(ceil(8*(v+1)) - 1, 0, 15).
__device__ __forceinline__ int bin_of(float v) {
    int i = __float2int_ru(fmaf(v, 8.0f, 8.0f)) - 1;   // single F2I.CEIL
    i = max(i, 0);
    i = min(i, 15);
    return i;
}

__device__ __forceinline__ int flat_bin(float r, float g, float b) {
    return bin_of(r) + (bin_of(g) << 4) + (bin_of(b) << 8);
}

// ---------------------------------------------------------------------------
// Kernel A: per-image histogram (round-8 config — best measured).
// grid = (BPI, NIMG), block = TPB. Skewed shared bins, 6-batched LDG.128,
// pruned 64-bit packed flush.
// ---------------------------------------------------------------------------
__global__ __launch_bounds__(TPB) void hist_kernel(
    const float* __restrict__ inp,   // [8, 3, H, W]
    const float* __restrict__ sty)   // [1, 3, H, W]
{
    __shared__ int sh[NTOT];         // 16 KB per-CTA histogram (skewed)
    #pragma unroll
    for (int i = threadIdx.x; i < NTOT; i += TPB) sh[i] = 0;
    __syncthreads();

    const int img = blockIdx.y;
    const float* base = (img < 8) ? (inp + (size_t)img * 3 * HW) : sty;

    const float4* r4 = (const float4*)(base);
    const float4* g4 = (const float4*)(base + HW);
    const float4* b4 = (const float4*)(base + 2 * HW);

    const int per_block = (HW / 4) / BPI;          // 2048 float4 per channel
    const int start     = blockIdx.x * per_block;
    const int end       = start + per_block;

    // 6 front-batched LDG.128 per iteration for explicit MLP, then 8 atomics.
    for (int i = start + threadIdx.x; i < end; i += 2 * TPB) {
        float4 ra = r4[i];
        float4 rb = r4[i + TPB];
        float4 ga = g4[i];
        float4 gb = g4[i + TPB];
        float4 ba = b4[i];
        float4 bb = b4[i + TPB];

        atomicAdd(&sh[skew(flat_bin(ra.x, ga.x, ba.x))], 1);
        atomicAdd(&sh[skew(flat_bin(ra.y, ga.y, ba.y))], 1);
        atomicAdd(&sh[skew(flat_bin(ra.z, ga.z, ba.z))], 1);
        atomicAdd(&sh[skew(flat_bin(ra.w, ga.w, ba.w))], 1);
        atomicAdd(&sh[skew(flat_bin(rb.x, gb.x, bb.x))], 1);
        atomicAdd(&sh[skew(flat_bin(rb.y, gb.y, bb.y))], 1);
        atomicAdd(&sh[skew(flat_bin(rb.z, gb.z, bb.z))], 1);
        atomicAdd(&sh[skew(flat_bin(rb.w, gb.w, bb.w))], 1);
    }
    __syncthreads();

    // Flush: unskew, pack two adjacent f-bins into one 64-bit atomic.
    #pragma unroll
    for (int fp = threadIdx.x; fp < NPAIR; fp += TPB) {
        unsigned int lo = (unsigned int)sh[skew(2 * fp)];
        unsigned int hi = (unsigned int)sh[skew(2 * fp + 1)];
        if (lo | hi) {
            atomicAdd(&g_hist2[img][fp],
                      (unsigned long long)lo | ((unsigned long long)hi << 32));
        }
    }
}

// ---------------------------------------------------------------------------
// Kernel B: parallel loss + scratch reset. grid = LOSS_CTAS, block = LOSS_TPB.
// Launched with PDL so its launch ramp overlaps the hist kernel's tail;
// cudaGridDependencySynchronize() gates the dependent reads.
// ---------------------------------------------------------------------------
__global__ __launch_bounds__(LOSS_TPB) void loss_kernel(float* __restrict__ out)
{
    cudaGridDependencySynchronize();   // wait for hist kernel's results

    const int i = blockIdx.x * LOSS_TPB + threadIdx.x;   // pair index, < NPAIR

    // 9 independent loads (batched for MLP)
    unsigned long long ps = g_hist2[8][i];
    unsigned long long p0 = g_hist2[0][i];
    unsigned long long p1 = g_hist2[1][i];
    unsigned long long p2 = g_hist2[2][i];
    unsigned long long p3 = g_hist2[3][i];
    unsigned long long p4 = g_hist2[4][i];
    unsigned long long p5 = g_hist2[5][i];
    unsigned long long p6 = g_hist2[6][i];
    unsigned long long p7 = g_hist2[7][i];

    int slo = (int)(unsigned int)ps;
    int shi = (int)(unsigned int)(ps >> 32);

    int acc = 0;   // max 2*8*HW = 16.8M < 2^31
    #define ABS_DIFF(p) do {                                   \
        int d0 = (int)(unsigned int)(p) - slo;                 \
        int d1 = (int)(unsigned int)((p) >> 32) - shi;         \
        acc += (d0 < 0 ? -d0 : d0) + (d1 < 0 ? -d1 : d1);      \
    } while (0)
    ABS_DIFF(p0); ABS_DIFF(p1); ABS_DIFF(p2); ABS_DIFF(p3);
    ABS_DIFF(p4); ABS_DIFF(p5); ABS_DIFF(p6); ABS_DIFF(p7);
    #undef ABS_DIFF

    // reset this thread's slice of the scratch for the next graph replay
    #pragma unroll
    for (int b = 0; b < NIMG; b++) g_hist2[b][i] = 0ULL;

    // block reduction
    #pragma unroll
    for (int o = 16; o > 0; o >>= 1)
        acc += __shfl_xor_sync(0xffffffffu, acc, o);

    __shared__ int warp_sum[LOSS_TPB / 32];
    if ((threadIdx.x & 31) == 0) warp_sum[threadIdx.x >> 5] = acc;
    __syncthreads();

    __shared__ unsigned int my_ticket;
    if (threadIdx.x == 0) {
        int blk = 0;
        #pragma unroll
        for (int w = 0; w < LOSS_TPB / 32; w++) blk += warp_sum[w];
        atomicAdd(&g_loss_acc, (unsigned int)blk);
        __threadfence();
        my_ticket = atomicAdd(&g_done, 1u);
    }
    __syncthreads();

    if (threadIdx.x == 0 && my_ticket == (unsigned int)(LOSS_CTAS - 1)) {
        unsigned int total = atomicAdd(&g_loss_acc, 0u);   // coherent read
        out[0] = (float)((double)total /
                         ((double)HW * 8.0 * (double)NTOT));
        g_loss_acc = 0u;
        g_done = 0u;
    }
}

// ---------------------------------------------------------------------------
// Launch contract
// ---------------------------------------------------------------------------
extern "C" void kernel_launch(void* const* d_in, const int* in_sizes, int n_in,
                              void* d_out, int out_size)
{
    const float* inp = (const float*)d_in[0];   // [8,3,1024,1024] fp32
    const float* sty = (const float*)d_in[1];   // [1,3,1024,1024] fp32
    float* out = (float*)d_out;

    dim3 grid(BPI, NIMG);
    hist_kernel<<<grid, TPB>>>(inp, sty);

    // Loss kernel with programmatic dependent launch (overlap launch ramp
    // with hist tail; cudaGridDependencySynchronize() inside orders reads).
    cudaLaunchConfig_t cfg = {};
    cfg.gridDim  = dim3(LOSS_CTAS, 1, 1);
    cfg.blockDim = dim3(LOSS_TPB, 1, 1);
    cfg.dynamicSmemBytes = 0;
    cfg.stream = 0;
    cudaLaunchAttribute attrs[1];
    attrs[0].id = cudaLaunchAttributeProgrammaticStreamSerialization;
    attrs[0].val.programmaticStreamSerializationAllowed = 1;
    cfg.attrs = attrs;
    cfg.numAttrs = 1;
    cudaLaunchKernelEx(&cfg, loss_kernel, out);
}